// round 7
// baseline (speedup 1.0000x reference)
#include <cuda_runtime.h>
#define TPB 512
typedef unsigned long long ull;

static __device__ __forceinline__ ull pk(float lo, float hi){ ull r; asm("mov.b64 %0,{%1,%2};":"=l"(r):"f"(lo),"f"(hi)); return r; }
static __device__ __forceinline__ void upk(ull v, float &lo, float &hi){ asm("mov.b64 {%0,%1},%2;":"=f"(lo),"=f"(hi):"l"(v)); }
static __device__ __forceinline__ void fma2(ull &d, ull a, ull b){ asm("fma.rn.f32x2 %0,%1,%2,%0;":"+l"(d):"l"(a),"l"(b)); }
static __device__ __forceinline__ float siluf(float z){ return z*(1.f/(1.f+__expf(-z))); }
static __device__ __forceinline__ float dsiluf(float z){ float s=1.f/(1.f+__expf(-z)); return s*(1.f+z*(1.f-s)); }

__device__ float g_cd[2][256];

// ---- SMEM float offsets ----
#define O_BASE 0                 // 256*32
#define O_TZ1  8192              // 256*32
#define O_EPS  16384             // 64*32
#define O_DR   18432             // 32
#define O_PB   18464             // 2*16*32
#define O_POOL 19488             // 32768 pool
#define O_A12  (O_POOL)          // 256*96 (primal l1/l2 acts, s: 0=f,1=u,2=v)
#define O_CND  (O_POOL+24576)    // 3*16*32
#define O_Y    (O_POOL+26112)    // 64*32
#define O_OUT3 (O_POOL)          // 3*128*32 overlay after layer3
#define O_AT1  (O_POOL)          // 256*128 (JVP quad: 0=pu,1=tu,2=pv,3=tv)
#define O_TA2  (O_POOL)          // 256*64 overlay after layer2d (0=tu,1=tv)
#define SMEM_FLOATS 52256

__global__ void precompute_k(const float* __restrict__ cu, const float* __restrict__ cv,
                             const float* __restrict__ W1){
    int c = threadIdx.x;
    float su = 0.f, sv = 0.f;
    #pragma unroll
    for (int j = 0; j < 16; j++){
        float w = __ldg(W1 + (65+j)*256 + c);
        su += __ldg(cu + j) * w;
        sv += __ldg(cv + j) * w;
    }
    g_cd[0][c] = su; g_cd[1][c] = sv;
}

__global__ void __launch_bounds__(TPB, 1) node_main(
    const float* __restrict__ gt, const float* __restrict__ gx, const float* __restrict__ geps,
    const float* __restrict__ gcu, const float* __restrict__ gcv, const float* __restrict__ gcf,
    const float* __restrict__ W1, const float* __restrict__ b1,
    const float* __restrict__ W2, const float* __restrict__ b2,
    const float* __restrict__ W3, const float* __restrict__ b3,
    float* __restrict__ out, int B)
{
    extern __shared__ float sm[];
    const int tid  = threadIdx.x;
    const int lane = tid & 31;
    const int wp   = tid >> 5;          // 16 warps
    const int row0 = blockIdx.x * 32;
    const int cw0  = 16*wp;             // 16-col slice (256-col passes)
    const int c8   = 8*wp;              // 8-col slice (layer3, 128 cols)
    const int c4   = 4*wp;              // 4-col slice (tl3, 64 cols)

    // ---- P0 ----
    for (int i = tid; i < 64*32; i += TPB){
        int r = i & 31, d = i >> 5; int gr = row0 + r;
        sm[O_Y   + d*32 + r] = (gr < B) ? gx[(size_t)gr*65 + d]  : 0.f;
        sm[O_EPS + d*32 + r] = (gr < B) ? geps[(size_t)gr*64 + d] : 0.f;
    }
    for (int i = tid; i < 3*16*32; i += TPB){
        int r = i & 31, j = (i >> 5) & 15, s = i >> 9;
        int gr = row0 + r; int gi = (gr < B) ? gr : 0;
        const float* src = (s == 0) ? gcf : ((s == 1) ? gcu : gcv);
        sm[O_CND + s*512 + j*32 + r] = src[(size_t)gi*16 + j];
    }
    if (tid < 32) sm[O_DR + tid] = 0.f;
    __syncthreads();

    // ---- fillBase: BASE = y@W1y + t*W1t + b1 ; TZ1 = e@W1y ----
    {
        ull ay[8], ae[8];
        #pragma unroll
        for (int j = 0; j < 8; j++){ ay[j] = 0ULL; ae[j] = 0ULL; }
        #pragma unroll 4
        for (int k = 0; k < 64; k++){
            float4 w0 = __ldg((const float4*)(W1 + k*256 + cw0));
            float4 w1 = __ldg((const float4*)(W1 + k*256 + cw0 + 4));
            float4 w2 = __ldg((const float4*)(W1 + k*256 + cw0 + 8));
            float4 w3 = __ldg((const float4*)(W1 + k*256 + cw0 + 12));
            ull wv[8] = {pk(w0.x,w0.y),pk(w0.z,w0.w),pk(w1.x,w1.y),pk(w1.z,w1.w),
                         pk(w2.x,w2.y),pk(w2.z,w2.w),pk(w3.x,w3.y),pk(w3.z,w3.w)};
            float yv = sm[O_Y + k*32 + lane], ev = sm[O_EPS + k*32 + lane];
            ull y2 = pk(yv,yv), e2 = pk(ev,ev);
            #pragma unroll
            for (int j = 0; j < 8; j++){ fma2(ay[j], y2, wv[j]); fma2(ae[j], e2, wv[j]); }
        }
        float tv = __ldg(gt);
        #pragma unroll
        for (int j = 0; j < 8; j++){
            int c = cw0 + 2*j;
            float s0 = tv*__ldg(W1 + 64*256 + c)   + __ldg(b1 + c);
            float s1 = tv*__ldg(W1 + 64*256 + c+1) + __ldg(b1 + c+1);
            float p0, p1, t0, t1;
            upk(ay[j], p0, p1); upk(ae[j], t0, t1);
            sm[O_BASE + c*32 + lane] = p0 + s0; sm[O_BASE + (c+1)*32 + lane] = p1 + s1;
            sm[O_TZ1  + c*32 + lane] = t0;      sm[O_TZ1  + (c+1)*32 + lane] = t1;
        }
    }
    __syncthreads();

    // ---- fillA1 fused (3 conds): A12 = silu(BASE + cond@W1c) ----
    {
        ull a[3][8];
        #pragma unroll
        for (int s = 0; s < 3; s++)
            #pragma unroll
            for (int j = 0; j < 8; j++) a[s][j] = 0ULL;
        #pragma unroll 4
        for (int k = 0; k < 16; k++){
            const float* wr = W1 + (65+k)*256 + cw0;
            float4 w0 = __ldg((const float4*)wr),     w1 = __ldg((const float4*)(wr+4));
            float4 w2 = __ldg((const float4*)(wr+8)), w3 = __ldg((const float4*)(wr+12));
            ull wv[8] = {pk(w0.x,w0.y),pk(w0.z,w0.w),pk(w1.x,w1.y),pk(w1.z,w1.w),
                         pk(w2.x,w2.y),pk(w2.z,w2.w),pk(w3.x,w3.y),pk(w3.z,w3.w)};
            #pragma unroll
            for (int s = 0; s < 3; s++){
                float cv = sm[O_CND + s*512 + k*32 + lane];
                ull c2 = pk(cv,cv);
                #pragma unroll
                for (int j = 0; j < 8; j++) fma2(a[s][j], c2, wv[j]);
            }
        }
        #pragma unroll
        for (int j = 0; j < 8; j++){
            int c = cw0 + 2*j;
            float b0 = sm[O_BASE + c*32 + lane], b1v = sm[O_BASE + (c+1)*32 + lane];
            #pragma unroll
            for (int s = 0; s < 3; s++){
                float d0, d1; upk(a[s][j], d0, d1);
                sm[O_A12 + c*96     + s*32 + lane] = siluf(b0 + d0);
                sm[O_A12 + (c+1)*96 + s*32 + lane] = siluf(b1v + d1);
            }
        }
    }
    __syncthreads();

    // ---- layer2 fused (3 streams): A12 <- silu(A12@W2 + b2) ----
    {
        ull a[3][8];
        #pragma unroll
        for (int s = 0; s < 3; s++)
            #pragma unroll
            for (int j = 0; j < 8; j++) a[s][j] = 0ULL;
        #pragma unroll 2
        for (int k = 0; k < 256; k++){
            const float* wr = W2 + k*256 + cw0;
            float4 w0 = __ldg((const float4*)wr),     w1 = __ldg((const float4*)(wr+4));
            float4 w2 = __ldg((const float4*)(wr+8)), w3 = __ldg((const float4*)(wr+12));
            ull wv[8] = {pk(w0.x,w0.y),pk(w0.z,w0.w),pk(w1.x,w1.y),pk(w1.z,w1.w),
                         pk(w2.x,w2.y),pk(w2.z,w2.w),pk(w3.x,w3.y),pk(w3.z,w3.w)};
            #pragma unroll
            for (int s = 0; s < 3; s++){
                float av = sm[O_A12 + k*96 + s*32 + lane];
                ull a2 = pk(av,av);
                #pragma unroll
                for (int j = 0; j < 8; j++) fma2(a[s][j], a2, wv[j]);
            }
        }
        __syncthreads();
        #pragma unroll
        for (int j = 0; j < 8; j++){
            int c = cw0 + 2*j;
            float bb0 = __ldg(b2 + c), bb1 = __ldg(b2 + c+1);
            #pragma unroll
            for (int s = 0; s < 3; s++){
                float d0, d1; upk(a[s][j], d0, d1);
                sm[O_A12 + c*96     + s*32 + lane] = siluf(d0 + bb0);
                sm[O_A12 + (c+1)*96 + s*32 + lane] = siluf(d1 + bb1);
            }
        }
    }
    __syncthreads();

    // ---- layer3 fused (3 streams, 128 cols) -> OUT3 ----
    {
        ull a[3][4];
        #pragma unroll
        for (int s = 0; s < 3; s++)
            #pragma unroll
            for (int j = 0; j < 4; j++) a[s][j] = 0ULL;
        #pragma unroll 2
        for (int k = 0; k < 256; k++){
            float4 wa = __ldg((const float4*)(W3 + k*128 + c8));
            float4 wb = __ldg((const float4*)(W3 + k*128 + c8 + 4));
            ull wv[4] = {pk(wa.x,wa.y),pk(wa.z,wa.w),pk(wb.x,wb.y),pk(wb.z,wb.w)};
            #pragma unroll
            for (int s = 0; s < 3; s++){
                float av = sm[O_A12 + k*96 + s*32 + lane];
                ull a2 = pk(av,av);
                #pragma unroll
                for (int j = 0; j < 4; j++) fma2(a[s][j], a2, wv[j]);
            }
        }
        __syncthreads();
        #pragma unroll
        for (int j = 0; j < 4; j++){
            int c = c8 + 2*j;
            float bb0 = __ldg(b3 + c), bb1 = __ldg(b3 + c+1);
            #pragma unroll
            for (int s = 0; s < 3; s++){
                float d0, d1; upk(a[s][j], d0, d1);
                sm[O_OUT3 + s*4096 + c*32 + lane]     = d0 + bb0;
                sm[O_OUT3 + s*4096 + (c+1)*32 + lane] = d1 + bb1;
            }
        }
    }
    __syncthreads();

    // ---- ft output + corrections (16 threads per row over 64 cols) ----
    {
        int cc = tid & 15, r = tid >> 4;
        int gr = row0 + r;
        float part = 0.f;
        #pragma unroll
        for (int j = 0; j < 4; j++){
            int c = 4*cc + j;
            float fv = sm[O_OUT3 + 0*4096 + c*32 + r];
            float uv = sm[O_OUT3 + 1*4096 + c*32 + r];
            float vv = sm[O_OUT3 + 2*4096 + c*32 + r];
            float su = sm[O_OUT3 + 1*4096 + (64+c)*32 + r];
            float sv = sm[O_OUT3 + 2*4096 + (64+c)*32 + r];
            part += (fv - uv)*su - (fv - vv)*sv;
            if (gr < B) out[(size_t)gr*65 + c] = fv;
        }
        part += __shfl_down_sync(0xffffffffu, part, 8, 16);
        part += __shfl_down_sync(0xffffffffu, part, 4, 16);
        part += __shfl_down_sync(0xffffffffu, part, 2, 16);
        part += __shfl_down_sync(0xffffffffu, part, 1, 16);
        if ((tid & 15) == 0) sm[O_DR + r] += part;
    }
    __syncthreads();

    // ---- fillJ quad: AT1 = {silu(zu), dsilu(zu)*tz, silu(zv), dsilu(zv)*tz} ----
    #pragma unroll 4
    for (int ci = 0; ci < 16; ci++){
        int c = cw0 + ci;
        float bs = sm[O_BASE + c*32 + lane];
        float tz = sm[O_TZ1  + c*32 + lane];
        float zu = bs + g_cd[0][c], zv = bs + g_cd[1][c];
        sm[O_AT1 + c*128 +      lane] = siluf(zu);
        sm[O_AT1 + c*128 + 32 + lane] = dsiluf(zu)*tz;
        sm[O_AT1 + c*128 + 64 + lane] = siluf(zv);
        sm[O_AT1 + c*128 + 96 + lane] = dsiluf(zv)*tz;
    }
    __syncthreads();

    // ---- layer2d quad: TA2 = dsilu(z2)*t2 for u,v ----
    {
        ull a[4][8];
        #pragma unroll
        for (int s = 0; s < 4; s++)
            #pragma unroll
            for (int j = 0; j < 8; j++) a[s][j] = 0ULL;
        #pragma unroll 2
        for (int k = 0; k < 256; k++){
            const float* wr = W2 + k*256 + cw0;
            float4 w0 = __ldg((const float4*)wr),     w1 = __ldg((const float4*)(wr+4));
            float4 w2 = __ldg((const float4*)(wr+8)), w3 = __ldg((const float4*)(wr+12));
            ull wv[8] = {pk(w0.x,w0.y),pk(w0.z,w0.w),pk(w1.x,w1.y),pk(w1.z,w1.w),
                         pk(w2.x,w2.y),pk(w2.z,w2.w),pk(w3.x,w3.y),pk(w3.z,w3.w)};
            #pragma unroll
            for (int s = 0; s < 4; s++){
                float av = sm[O_AT1 + k*128 + s*32 + lane];
                ull a2 = pk(av,av);
                #pragma unroll
                for (int j = 0; j < 8; j++) fma2(a[s][j], a2, wv[j]);
            }
        }
        __syncthreads();
        #pragma unroll
        for (int j = 0; j < 8; j++){
            int c = cw0 + 2*j;
            float bb0 = __ldg(b2 + c), bb1 = __ldg(b2 + c+1);
            float zu0, zu1, tu0, tu1, zv0, zv1, tv0, tv1;
            upk(a[0][j], zu0, zu1); upk(a[1][j], tu0, tu1);
            upk(a[2][j], zv0, zv1); upk(a[3][j], tv0, tv1);
            sm[O_TA2 + c*64      + lane] = dsiluf(zu0 + bb0)*tu0;
            sm[O_TA2 + c*64 + 32 + lane] = dsiluf(zv0 + bb0)*tv0;
            sm[O_TA2 + (c+1)*64      + lane] = dsiluf(zu1 + bb1)*tu1;
            sm[O_TA2 + (c+1)*64 + 32 + lane] = dsiluf(zv1 + bb1)*tv1;
        }
    }
    __syncthreads();

    // ---- tl3 fused (u,v): partials of eps-dot into PB ----
    {
        ull a[2][2];
        a[0][0]=0ULL; a[0][1]=0ULL; a[1][0]=0ULL; a[1][1]=0ULL;
        #pragma unroll 4
        for (int k = 0; k < 256; k++){
            float4 w = __ldg((const float4*)(W3 + k*128 + c4));
            ull wv[2] = {pk(w.x,w.y), pk(w.z,w.w)};
            float tu = sm[O_TA2 + k*64 + lane], tv = sm[O_TA2 + k*64 + 32 + lane];
            ull u2 = pk(tu,tu), v2 = pk(tv,tv);
            fma2(a[0][0], u2, wv[0]); fma2(a[0][1], u2, wv[1]);
            fma2(a[1][0], v2, wv[0]); fma2(a[1][1], v2, wv[1]);
        }
        float pu = 0.f, pv = 0.f;
        #pragma unroll
        for (int j = 0; j < 2; j++){
            int c = c4 + 2*j;
            float e0 = sm[O_EPS + c*32 + lane], e1 = sm[O_EPS + (c+1)*32 + lane];
            float x0, x1, y0, y1;
            upk(a[0][j], x0, x1); upk(a[1][j], y0, y1);
            pu += x0*e0 + x1*e1;
            pv += y0*e0 + y1*e1;
        }
        sm[O_PB +       wp*32 + lane] = pu;
        sm[O_PB + 512 + wp*32 + lane] = pv;
    }
    __syncthreads();

    // ---- finalize dr: div = e.(Jv e) - e.(Ju e) ----
    if (tid < 32){
        float dv = 0.f;
        #pragma unroll
        for (int w2 = 0; w2 < 16; w2++)
            dv += sm[O_PB + 512 + w2*32 + tid] - sm[O_PB + w2*32 + tid];
        int gr = row0 + tid;
        if (gr < B) out[(size_t)gr*65 + 64] = sm[O_DR + tid] + dv;
    }
}

extern "C" void kernel_launch(void* const* d_in, const int* in_sizes, int n_in,
                              void* d_out, int out_size)
{
    const float* gt  = (const float*)d_in[0];
    const float* gx  = (const float*)d_in[1];
    const float* ge  = (const float*)d_in[2];
    const float* gcu = (const float*)d_in[3];
    const float* gcv = (const float*)d_in[4];
    const float* gcf = (const float*)d_in[5];
    const float* W1  = (const float*)d_in[6];
    const float* b1  = (const float*)d_in[7];
    const float* W2  = (const float*)d_in[8];
    const float* b2  = (const float*)d_in[9];
    const float* W3  = (const float*)d_in[10];
    const float* b3  = (const float*)d_in[11];
    float* out = (float*)d_out;

    int B = in_sizes[1] / 65;
    int grid = (B + 31) / 32;

    cudaFuncSetAttribute(node_main, cudaFuncAttributeMaxDynamicSharedMemorySize, SMEM_FLOATS*4);

    precompute_k<<<1, 256>>>(gcu, gcv, W1);
    node_main<<<grid, TPB, SMEM_FLOATS*4>>>(gt, gx, ge, gcu, gcv, gcf,
                                            W1, b1, W2, b2, W3, b3, out, B);
}

// round 8
// speedup vs baseline: 1.1281x; 1.1281x over previous
#include <cuda_runtime.h>
#define TPB 512
typedef unsigned long long ull;

static __device__ __forceinline__ ull pk(float lo, float hi){ ull r; asm("mov.b64 %0,{%1,%2};":"=l"(r):"f"(lo),"f"(hi)); return r; }
static __device__ __forceinline__ void upk(ull v, float &lo, float &hi){ asm("mov.b64 {%0,%1},%2;":"=f"(lo),"=f"(hi):"l"(v)); }
static __device__ __forceinline__ void fma2(ull &d, ull a, ull b){ asm("fma.rn.f32x2 %0,%1,%2,%0;":"+l"(d):"l"(a),"l"(b)); }
static __device__ __forceinline__ float siluf(float z){ return z*(1.f/(1.f+__expf(-z))); }
static __device__ __forceinline__ float dsiluf(float z){ float s=1.f/(1.f+__expf(-z)); return s*(1.f+z*(1.f-s)); }

__device__ float g_cd[2][256];

// ---- SMEM float offsets ----
#define O_WE   0        // 8192   WE[c][r]
#define O_BASE 8192     // 8192   [c][r]; JVP phase: weight panel
#define O_TZ1  16384    // 8192
#define O_POOL 24576    // 32768
#define O_DR   57344    // 32
#define O_PB   57376    // 128
#define SMEM_FLOATS 57504
// pool-relative temps
#define P_W3T  0        // 64*260 = 16640
#define P_Y    16640    // 2048
#define P_EPS  18688    // 2048
#define P_WPAN 24576    // 4096 (primal panels)
#define P_CND  29696    // 1536

__global__ void precompute_k(const float* __restrict__ cu, const float* __restrict__ cv,
                             const float* __restrict__ W1){
    int c = threadIdx.x;
    float su = 0.f, sv = 0.f;
    #pragma unroll
    for (int j = 0; j < 16; j++){
        float w = __ldg(W1 + (65+j)*256 + c);
        su += __ldg(cu + j) * w;
        sv += __ldg(cv + j) * w;
    }
    g_cd[0][c] = su; g_cd[1][c] = sv;
}

// thread tile 4 cols x 16 rows; acc[rowpair][col]; acts uniform rowpair ulls
static __device__ __forceinline__ void mma4(ull (&acc)[8][4], const float* actp, float4 w){
    ull wd[4] = {pk(w.x,w.x), pk(w.y,w.y), pk(w.z,w.z), pk(w.w,w.w)};
    ulonglong2 a0 = *reinterpret_cast<const ulonglong2*>(actp);
    ulonglong2 a1 = *reinterpret_cast<const ulonglong2*>(actp + 4);
    ulonglong2 a2 = *reinterpret_cast<const ulonglong2*>(actp + 8);
    ulonglong2 a3 = *reinterpret_cast<const ulonglong2*>(actp + 12);
    ull ar[8] = {a0.x,a0.y,a1.x,a1.y,a2.x,a2.y,a3.x,a3.y};
    #pragma unroll
    for (int rp = 0; rp < 8; rp++){
        #pragma unroll
        for (int c = 0; c < 4; c++) fma2(acc[rp][c], ar[rp], wd[c]);
    }
}
// 2-col variant
static __device__ __forceinline__ void mma2c(ull (&acc)[8][2], const float* actp, float2 w){
    ull wd[2] = {pk(w.x,w.x), pk(w.y,w.y)};
    ulonglong2 a0 = *reinterpret_cast<const ulonglong2*>(actp);
    ulonglong2 a1 = *reinterpret_cast<const ulonglong2*>(actp + 4);
    ulonglong2 a2 = *reinterpret_cast<const ulonglong2*>(actp + 8);
    ulonglong2 a3 = *reinterpret_cast<const ulonglong2*>(actp + 12);
    ull ar[8] = {a0.x,a0.y,a1.x,a1.y,a2.x,a2.y,a3.x,a3.y};
    #pragma unroll
    for (int rp = 0; rp < 8; rp++){
        #pragma unroll
        for (int c = 0; c < 2; c++) fma2(acc[rp][c], ar[rp], wd[c]);
    }
}

__global__ void __launch_bounds__(TPB, 1) node_main(
    const float* __restrict__ gt, const float* __restrict__ gx, const float* __restrict__ geps,
    const float* __restrict__ gcu, const float* __restrict__ gcv, const float* __restrict__ gcf,
    const float* __restrict__ W1, const float* __restrict__ b1,
    const float* __restrict__ W2, const float* __restrict__ b2,
    const float* __restrict__ W3, const float* __restrict__ b3,
    float* __restrict__ out, int B)
{
    extern __shared__ float sm[];
    const int tid  = threadIdx.x;
    const int lane = tid & 31;
    const int wp   = tid >> 5;
    const int row0 = blockIdx.x * 32;

    // ---- P0: tiles + W3 transpose ----
    for (int i = tid; i < 64*32; i += TPB){
        int r = i & 31, d = i >> 5; int gr = row0 + r;
        sm[O_POOL + P_Y   + d*32 + r] = (gr < B) ? gx[(size_t)gr*65 + d]  : 0.f;
        sm[O_POOL + P_EPS + d*32 + r] = (gr < B) ? geps[(size_t)gr*64 + d] : 0.f;
    }
    for (int i = tid; i < 3*16*32; i += TPB){
        int r = i & 31, j = (i >> 5) & 15, s = i >> 9;
        int gr = row0 + r; int gi = (gr < B) ? gr : 0;
        const float* src = (s == 0) ? gcf : ((s == 1) ? gcu : gcv);
        sm[O_POOL + P_CND + s*512 + j*32 + r] = src[(size_t)gi*16 + j];
    }
    for (int i = tid; i < 256*64; i += TPB){
        int k = i >> 6, j = i & 63;
        sm[O_POOL + P_W3T + j*260 + k] = __ldg(W3 + k*128 + j);
    }
    if (tid < 32) sm[O_DR + tid] = 0.f;
    __syncthreads();

    // ---- fillBase (warps 0-7) + WE (warps 8-15) ----
    if (wp < 8){
        int s = wp >> 2, cb = (wp >> 1) & 1, rb = wp & 1;
        int c0 = cb*128 + 4*lane, r0 = rb*16;
        ull acc[8][4];
        #pragma unroll
        for (int i = 0; i < 8; i++){ acc[i][0]=0; acc[i][1]=0; acc[i][2]=0; acc[i][3]=0; }
        const float* act = sm + O_POOL + (s == 0 ? P_Y : P_EPS) + r0;
        #pragma unroll 4
        for (int k = 0; k < 64; k++)
            mma4(acc, act + k*32, __ldg((const float4*)(W1 + k*256 + c0)));
        if (s == 0){
            float tv = __ldg(gt);
            float4 wt = __ldg((const float4*)(W1 + 64*256 + c0));
            float4 bb = __ldg((const float4*)(b1 + c0));
            float sA[4] = {tv*wt.x + bb.x, tv*wt.y + bb.y, tv*wt.z + bb.z, tv*wt.w + bb.w};
            #pragma unroll
            for (int j = 0; j < 4; j++)
                #pragma unroll
                for (int rp = 0; rp < 8; rp++){
                    float lo, hi; upk(acc[rp][j], lo, hi);
                    *(float2*)(sm + O_BASE + (c0+j)*32 + r0 + 2*rp) = make_float2(lo + sA[j], hi + sA[j]);
                }
        } else {
            #pragma unroll
            for (int j = 0; j < 4; j++)
                #pragma unroll
                for (int rp = 0; rp < 8; rp++){
                    float lo, hi; upk(acc[rp][j], lo, hi);
                    *(float2*)(sm + O_TZ1 + (c0+j)*32 + r0 + 2*rp) = make_float2(lo, hi);
                }
        }
    } else {
        int w8 = wp - 8, cb = w8 >> 1, rb = w8 & 1;
        int c0 = cb*64 + 2*lane, r0 = rb*16;
        ull acc[8][2];
        #pragma unroll
        for (int i = 0; i < 8; i++){ acc[i][0]=0; acc[i][1]=0; }
        const float* act = sm + O_POOL + P_EPS + r0;
        #pragma unroll 4
        for (int j = 0; j < 64; j++)
            mma2c(acc, act + j*32, *(const float2*)(sm + O_POOL + P_W3T + j*260 + c0));
        #pragma unroll
        for (int j = 0; j < 2; j++)
            #pragma unroll
            for (int rp = 0; rp < 8; rp++){
                float lo, hi; upk(acc[rp][j], lo, hi);
                *(float2*)(sm + O_WE + (c0+j)*32 + r0 + 2*rp) = make_float2(lo, hi);
            }
    }
    __syncthreads();

    const int sA = wp >> 2, cbA = (wp >> 1) & 1, rbA = wp & 1;   // 12/16-tile mapping
    const int c0A = cbA*128 + 4*lane, r0A = rbA*16;

    // ---- fillA1 (3 conds, K=16) ----
    if (wp < 12){
        ull acc[8][4];
        #pragma unroll
        for (int i = 0; i < 8; i++){ acc[i][0]=0; acc[i][1]=0; acc[i][2]=0; acc[i][3]=0; }
        const float* act = sm + O_POOL + P_CND + sA*512 + r0A;
        #pragma unroll
        for (int k = 0; k < 16; k++)
            mma4(acc, act + k*32, __ldg((const float4*)(W1 + (65+k)*256 + c0A)));
        #pragma unroll
        for (int j = 0; j < 4; j++)
            #pragma unroll
            for (int rp = 0; rp < 8; rp++){
                float lo, hi; upk(acc[rp][j], lo, hi);
                float2 b = *(const float2*)(sm + O_BASE + (c0A+j)*32 + r0A + 2*rp);
                *(float2*)(sm + O_POOL + sA*8192 + (c0A+j)*32 + r0A + 2*rp) =
                    make_float2(siluf(lo + b.x), siluf(hi + b.y));
            }
    }
    __syncthreads();

    // ---- layer2 primal (12 tiles, W2 via 16-k SMEM panels) ----
    {
        ull acc[8][4];
        #pragma unroll
        for (int i = 0; i < 8; i++){ acc[i][0]=0; acc[i][1]=0; acc[i][2]=0; acc[i][3]=0; }
        for (int p = 0; p < 16; p++){
            int off = tid*4;
            float4 v0 = __ldg((const float4*)(W2 + p*4096 + off));
            float4 v1 = __ldg((const float4*)(W2 + p*4096 + 2048 + off));
            *(float4*)(sm + O_POOL + P_WPAN + off) = v0;
            *(float4*)(sm + O_POOL + P_WPAN + 2048 + off) = v1;
            __syncthreads();
            if (wp < 12){
                const float* act = sm + O_POOL + sA*8192 + r0A;
                #pragma unroll
                for (int kk = 0; kk < 16; kk++)
                    mma4(acc, act + (p*16+kk)*32, *(const float4*)(sm + O_POOL + P_WPAN + kk*256 + c0A));
            }
            __syncthreads();
        }
        if (wp < 12){
            float4 bb = __ldg((const float4*)(b2 + c0A));
            float bbA[4] = {bb.x, bb.y, bb.z, bb.w};
            #pragma unroll
            for (int j = 0; j < 4; j++)
                #pragma unroll
                for (int rp = 0; rp < 8; rp++){
                    float lo, hi; upk(acc[rp][j], lo, hi);
                    *(float2*)(sm + O_POOL + sA*8192 + (c0A+j)*32 + r0A + 2*rp) =
                        make_float2(siluf(lo + bbA[j]), siluf(hi + bbA[j]));
                }
        }
    }
    __syncthreads();

    // ---- layer3 primal (12 tiles, 2c x 16r, W3 via panels) ----
    {
        ull acc[8][2];
        #pragma unroll
        for (int i = 0; i < 8; i++){ acc[i][0]=0; acc[i][1]=0; }
        int c03 = cbA*64 + 2*lane;
        for (int p = 0; p < 16; p++){
            int off = tid*4;
            float4 v = __ldg((const float4*)(W3 + p*2048 + off));
            *(float4*)(sm + O_POOL + P_WPAN + off) = v;
            __syncthreads();
            if (wp < 12){
                const float* act = sm + O_POOL + sA*8192 + r0A;
                #pragma unroll
                for (int kk = 0; kk < 16; kk++)
                    mma2c(acc, act + (p*16+kk)*32, *(const float2*)(sm + O_POOL + P_WPAN + kk*128 + c03));
            }
            __syncthreads();
        }
        if (wp < 12){
            float bb0 = __ldg(b3 + c03), bb1 = __ldg(b3 + c03 + 1);
            #pragma unroll
            for (int rp = 0; rp < 8; rp++){
                float lo, hi; upk(acc[rp][0], lo, hi);
                *(float2*)(sm + O_POOL + sA*4096 + c03*32 + r0A + 2*rp) = make_float2(lo+bb0, hi+bb0);
                upk(acc[rp][1], lo, hi);
                *(float2*)(sm + O_POOL + sA*4096 + (c03+1)*32 + r0A + 2*rp) = make_float2(lo+bb1, hi+bb1);
            }
        }
    }
    __syncthreads();

    // ---- ft output + corrections ----
    {
        int cc = tid & 15, r = tid >> 4;
        int gr = row0 + r;
        float part = 0.f;
        #pragma unroll
        for (int j = 0; j < 4; j++){
            int c = 4*cc + j;
            float fv = sm[O_POOL + 0*4096 + c*32 + r];
            float uv = sm[O_POOL + 1*4096 + c*32 + r];
            float vv = sm[O_POOL + 2*4096 + c*32 + r];
            float su = sm[O_POOL + 1*4096 + (64+c)*32 + r];
            float sv = sm[O_POOL + 2*4096 + (64+c)*32 + r];
            part += (fv - uv)*su - (fv - vv)*sv;
            if (gr < B) out[(size_t)gr*65 + c] = fv;
        }
        part += __shfl_down_sync(0xffffffffu, part, 8, 16);
        part += __shfl_down_sync(0xffffffffu, part, 4, 16);
        part += __shfl_down_sync(0xffffffffu, part, 2, 16);
        part += __shfl_down_sync(0xffffffffu, part, 1, 16);
        if ((tid & 15) == 0) sm[O_DR + r] += part;
    }
    __syncthreads();

    // ---- fillJ: AT1 quad (0=pu,1=tu,2=pv,3=tv) ----
    #pragma unroll 4
    for (int ci = 0; ci < 16; ci++){
        int c = wp*16 + ci;
        float bs = sm[O_BASE + c*32 + lane];
        float tz = sm[O_TZ1  + c*32 + lane];
        float zu = bs + g_cd[0][c], zv = bs + g_cd[1][c];
        sm[O_POOL + 0*8192 + c*32 + lane] = siluf(zu);
        sm[O_POOL + 1*8192 + c*32 + lane] = dsiluf(zu)*tz;
        sm[O_POOL + 2*8192 + c*32 + lane] = siluf(zv);
        sm[O_POOL + 3*8192 + c*32 + lane] = dsiluf(zv)*tz;
    }
    __syncthreads();

    // ---- layer2 JVP (16 tiles), panels staged into O_BASE region ----
    {
        ull acc[8][4];
        #pragma unroll
        for (int i = 0; i < 8; i++){ acc[i][0]=0; acc[i][1]=0; acc[i][2]=0; acc[i][3]=0; }
        for (int p = 0; p < 16; p++){
            int off = tid*4;
            float4 v0 = __ldg((const float4*)(W2 + p*4096 + off));
            float4 v1 = __ldg((const float4*)(W2 + p*4096 + 2048 + off));
            *(float4*)(sm + O_BASE + off) = v0;
            *(float4*)(sm + O_BASE + 2048 + off) = v1;
            __syncthreads();
            const float* act = sm + O_POOL + sA*8192 + r0A;
            #pragma unroll
            for (int kk = 0; kk < 16; kk++)
                mma4(acc, act + (p*16+kk)*32, *(const float4*)(sm + O_BASE + kk*256 + c0A));
            __syncthreads();
        }
        if ((sA & 1) == 0){
            // primal streams: write raw z2 over own (dead) AT1 slot
            #pragma unroll
            for (int j = 0; j < 4; j++)
                #pragma unroll
                for (int rp = 0; rp < 8; rp++){
                    float lo, hi; upk(acc[rp][j], lo, hi);
                    *(float2*)(sm + O_POOL + sA*8192 + (c0A+j)*32 + r0A + 2*rp) = make_float2(lo, hi);
                }
        }
        __syncthreads();
        if (sA & 1){
            float prow[16];
            #pragma unroll
            for (int i = 0; i < 16; i++) prow[i] = 0.f;
            const float* z2p = sm + O_POOL + (sA-1)*8192;
            float4 bb = __ldg((const float4*)(b2 + c0A));
            float bbA[4] = {bb.x, bb.y, bb.z, bb.w};
            #pragma unroll
            for (int j = 0; j < 4; j++){
                int c = c0A + j;
                #pragma unroll
                for (int rp = 0; rp < 8; rp++){
                    float2 z  = *(const float2*)(z2p + c*32 + r0A + 2*rp);
                    float2 we = *(const float2*)(sm + O_WE + c*32 + r0A + 2*rp);
                    float t0, t1; upk(acc[rp][j], t0, t1);
                    prow[2*rp]   += dsiluf(z.x + bbA[j]) * t0 * we.x;
                    prow[2*rp+1] += dsiluf(z.y + bbA[j]) * t1 * we.y;
                }
            }
            #pragma unroll
            for (int off = 16; off >= 1; off >>= 1)
                #pragma unroll
                for (int i = 0; i < 16; i++)
                    prow[i] += __shfl_down_sync(0xffffffffu, prow[i], off);
            if (lane == 0){
                int q = (sA >> 1)*2 + cbA;
                #pragma unroll
                for (int i = 0; i < 16; i++) sm[O_PB + q*32 + r0A + i] = prow[i];
            }
        }
    }
    __syncthreads();

    // ---- finalize: dr = corr - e.(Ju e) + e.(Jv e) ----
    if (tid < 32){
        float dr = sm[O_DR + tid]
                 - (sm[O_PB + tid] + sm[O_PB + 32 + tid])
                 + (sm[O_PB + 64 + tid] + sm[O_PB + 96 + tid]);
        int gr = row0 + tid;
        if (gr < B) out[(size_t)gr*65 + 64] = dr;
    }
}

extern "C" void kernel_launch(void* const* d_in, const int* in_sizes, int n_in,
                              void* d_out, int out_size)
{
    const float* gt  = (const float*)d_in[0];
    const float* gx  = (const float*)d_in[1];
    const float* ge  = (const float*)d_in[2];
    const float* gcu = (const float*)d_in[3];
    const float* gcv = (const float*)d_in[4];
    const float* gcf = (const float*)d_in[5];
    const float* W1  = (const float*)d_in[6];
    const float* b1  = (const float*)d_in[7];
    const float* W2  = (const float*)d_in[8];
    const float* b2  = (const float*)d_in[9];
    const float* W3  = (const float*)d_in[10];
    const float* b3  = (const float*)d_in[11];
    float* out = (float*)d_out;

    int B = in_sizes[1] / 65;
    int grid = (B + 31) / 32;

    cudaFuncSetAttribute(node_main, cudaFuncAttributeMaxDynamicSharedMemorySize, SMEM_FLOATS*4);

    precompute_k<<<1, 256>>>(gcu, gcv, W1);
    node_main<<<grid, TPB, SMEM_FLOATS*4>>>(gt, gx, ge, gcu, gcv, gcf,
                                            W1, b1, W2, b2, W3, b3, out, B);
}